// round 1
// baseline (speedup 1.0000x reference)
#include <cuda_runtime.h>

// Problem constants (from reference):
//   x1:   (16, 1, 224, 224) fp32
//   W:    (288, 1, 3, 3)    fp32
//   bias: (1, 288, 222, 222) fp32
//   out:  (16, 288, 222, 222) fp32 = relu(conv_valid(x1, W) + bias)

#define B_      16
#define COUT_   288
#define HIN_    224
#define WIN_    224
#define K_      3
#define HOUT_   222
#define WOUT_   222
#define PLANE_  (HOUT_ * WOUT_)   // 49284

__global__ __launch_bounds__(224) void conv_bias_relu_kernel(
    const float* __restrict__ x,
    const float* __restrict__ Wt,
    const float* __restrict__ bias,
    float* __restrict__ out)
{
    __shared__ float sW[COUT_ * 9];      // 10368 B
    __shared__ float sIn[3][WIN_];       //  2688 B

    const int h = blockIdx.x;            // 0..221
    const int b = blockIdx.y;            // 0..15
    const int t = threadIdx.x;           // 0..223

    // Cooperative load: all 288*9 weights into smem.
    #pragma unroll
    for (int i = t; i < COUT_ * 9; i += 224) sW[i] = Wt[i];

    // Cooperative load: the 3 input rows this output row needs.
    const float* xb = x + (long)b * HIN_ * WIN_;
    #pragma unroll
    for (int r = 0; r < 3; r++) sIn[r][t] = xb[(h + r) * WIN_ + t];

    __syncthreads();

    if (t >= WOUT_) return;

    // Hoist the 9 input taps into registers — invariant across all 288 channels.
    const float i00 = sIn[0][t], i01 = sIn[0][t + 1], i02 = sIn[0][t + 2];
    const float i10 = sIn[1][t], i11 = sIn[1][t + 1], i12 = sIn[1][t + 2];
    const float i20 = sIn[2][t], i21 = sIn[2][t + 1], i22 = sIn[2][t + 2];

    const long ofs = (long)h * WOUT_ + t;
    const float* bp = bias + ofs;                       // advances by PLANE_ per channel
    float*       op = out + (long)b * COUT_ * PLANE_ + ofs;

    // Channel loop: 9 FMA + 1 bias load (L2-hit) + 1 coalesced store per iter.
    // Unroll 4 for bias-load MLP.
    #pragma unroll 4
    for (int c = 0; c < COUT_; c++) {
        const float* w = sW + c * 9;
        float y = i00 * w[0];
        y = fmaf(i01, w[1], y);
        y = fmaf(i02, w[2], y);
        y = fmaf(i10, w[3], y);
        y = fmaf(i11, w[4], y);
        y = fmaf(i12, w[5], y);
        y = fmaf(i20, w[6], y);
        y = fmaf(i21, w[7], y);
        y = fmaf(i22, w[8], y);
        y += __ldg(bp);
        *op = fmaxf(y, 0.0f);
        bp += PLANE_;
        op += PLANE_;
    }
}

extern "C" void kernel_launch(void* const* d_in, const int* in_sizes, int n_in,
                              void* d_out, int out_size)
{
    const float* x    = (const float*)d_in[0];   // (16,1,224,224)
    const float* Wt   = (const float*)d_in[1];   // (288,1,3,3)
    const float* bias = (const float*)d_in[2];   // (1,288,222,222)
    float*       out  = (float*)d_out;           // (16,288,222,222)

    dim3 grid(HOUT_, B_);    // 222 x 16 = 3552 CTAs
    dim3 block(224);         // 7 warps; lanes 222..223 idle in compute
    conv_bias_relu_kernel<<<grid, block>>>(x, Wt, bias, out);
}

// round 2
// speedup vs baseline: 1.1519x; 1.1519x over previous
#include <cuda_runtime.h>

// x1:   (16, 1, 224, 224) fp32
// W:    (288, 1, 3, 3)    fp32
// bias: (1, 288, 222, 222) fp32
// out:  (16, 288, 222, 222) fp32 = relu(conv_valid(x1, W) + bias)

#define B_      16
#define COUT_   288
#define HIN_    224
#define WIN_    224
#define HOUT_   222
#define WOUT_   222
#define PLANE_  (HOUT_ * WOUT_)   // 49284
#define RPB     6                 // output rows per CTA (222 = 37*6)
#define IROWS   (RPB + 2)         // input rows needed = 8

__global__ __launch_bounds__(224, 4) void conv_bias_relu_kernel(
    const float* __restrict__ x,
    const float* __restrict__ Wt,
    const float* __restrict__ bias,
    float* __restrict__ out)
{
    // Weights padded to 12 floats/channel so each channel is 16B-aligned:
    // per channel read = 2x LDS.128 + 1x LDS.32 (3 wavefronts, not 9).
    __shared__ __align__(16) float sW[COUT_ * 12];   // 13824 B
    __shared__ float sIn[IROWS][WIN_];               //  7168 B

    const int hg = blockIdx.x;           // 0..36  (row group)
    const int b  = blockIdx.y;           // 0..15
    const int t  = threadIdx.x;          // 0..223
    const int h0 = hg * RPB;

    // Cooperative weight load with 9->12 padding.
    for (int i = t; i < COUT_ * 9; i += 224) {
        int c = i / 9, j = i - c * 9;
        sW[c * 12 + j] = Wt[i];
    }

    // Cooperative load of the 8 input rows this CTA needs (each thread = 1 col).
    const float* xb = x + (long)b * HIN_ * WIN_;
    #pragma unroll
    for (int r = 0; r < IROWS; r++) sIn[r][t] = xb[(h0 + r) * WIN_ + t];

    __syncthreads();

    if (t >= WOUT_) return;

    // 24 taps in registers: rows h0..h0+7, cols t..t+2. Invariant over channels.
    float tap[IROWS][3];
    #pragma unroll
    for (int r = 0; r < IROWS; r++) {
        tap[r][0] = sIn[r][t];
        tap[r][1] = sIn[r][t + 1];
        tap[r][2] = sIn[r][t + 2];
    }

    const long ofs = (long)h0 * WOUT_ + t;
    const float* bp = bias + ofs;
    float*       op = out + (long)b * COUT_ * PLANE_ + ofs;

    #pragma unroll 2
    for (int c = 0; c < COUT_; c++) {
        const float4 wA = *reinterpret_cast<const float4*>(&sW[c * 12]);     // w0..w3
        const float4 wB = *reinterpret_cast<const float4*>(&sW[c * 12 + 4]); // w4..w7
        const float  w8 = sW[c * 12 + 8];

        #pragma unroll
        for (int r = 0; r < RPB; r++) {
            float y = tap[r][0] * wA.x;
            y = fmaf(tap[r    ][1], wA.y, y);
            y = fmaf(tap[r    ][2], wA.z, y);
            y = fmaf(tap[r + 1][0], wA.w, y);
            y = fmaf(tap[r + 1][1], wB.x, y);
            y = fmaf(tap[r + 1][2], wB.y, y);
            y = fmaf(tap[r + 2][0], wB.z, y);
            y = fmaf(tap[r + 2][1], wB.w, y);
            y = fmaf(tap[r + 2][2], w8,  y);
            y += __ldg(bp + r * WOUT_);
            op[r * WOUT_] = fmaxf(y, 0.0f);
        }
        bp += PLANE_;
        op += PLANE_;
    }
}

extern "C" void kernel_launch(void* const* d_in, const int* in_sizes, int n_in,
                              void* d_out, int out_size)
{
    const float* x    = (const float*)d_in[0];
    const float* Wt   = (const float*)d_in[1];
    const float* bias = (const float*)d_in[2];
    float*       out  = (float*)d_out;

    dim3 grid(HOUT_ / RPB, B_);   // 37 x 16 = 592 CTAs
    dim3 block(224);              // 7 warps
    conv_bias_relu_kernel<<<grid, block>>>(x, Wt, bias, out);
}